// round 3
// baseline (speedup 1.0000x reference)
#include <cuda_runtime.h>

// Unfold (im2col): x[16,96,56,56] f32, 3x3 window, pad 1
// out[(bc*9 + ki*3+kj)*3136 + h*56+w] = x_pad[bc][h+ki][w+kj]
//
// One thread = (bc, h, w4). Per thread: 3 aligned LDG.128 (rows h-1,h,h+1),
// halo values fetched from neighbor lanes via warp shuffle (lanes hold
// consecutive w-chunks; at row wraps the halo is padding-zero anyway),
// then 9 streaming STG.128. Load-side L1 traffic ~halved vs v2.

#define B_ 16
#define C_ 96
#define H_ 56
#define W_ 56
#define HW_ (H_ * W_)        // 3136
#define HW4_ (HW_ / 4)       // 784
#define NTHREADS_ (B_ * C_ * HW4_)   // 1,204,224 = 4704 * 256 exactly

__global__ __launch_bounds__(256) void unfold_kernel(
    const float* __restrict__ x, float* __restrict__ out)
{
    int tid  = blockIdx.x * 256 + threadIdx.x;   // grid exact, no guard
    int lane = threadIdx.x & 31;

    int p4 = tid % HW4_;
    int bc = tid / HW4_;
    int p  = p4 * 4;
    int h  = p / W_;
    int w  = p - h * W_;      // multiple of 4

    const float* base  = x   + (size_t)bc * HW_;
    float*       obase = out + (size_t)bc * 9 * HW_ + p;

    #pragma unroll
    for (int r = 0; r < 3; r++) {
        int  sh = h + r - 1;
        bool ok = (sh >= 0) & (sh < H_);
        const float* rp = base + sh * W_ + w;

        float4 m = make_float4(0.f, 0.f, 0.f, 0.f);
        if (ok) m = *reinterpret_cast<const float4*>(rp);   // predicated LDG.128

        // halo from neighbor lanes (converged shuffles, full mask)
        float left  = __shfl_up_sync(0xffffffffu, m.w, 1);
        float right = __shfl_down_sync(0xffffffffu, m.x, 1);

        // warp-boundary lanes fall back to a scalar load (rare: 2/warp/row)
        if (lane == 0  && ok && w > 0)      left  = __ldg(rp - 1);
        if (lane == 31 && ok && w + 4 < W_) right = __ldg(rp + 4);

        // image-edge padding (also discards stale cross-row shuffle values)
        if (w == 0)       left  = 0.f;
        if (w + 4 >= W_)  right = 0.f;

        float* o = obase + (size_t)(r * 3) * HW_;
        __stcs(reinterpret_cast<float4*>(o),           make_float4(left, m.x, m.y, m.z));
        __stcs(reinterpret_cast<float4*>(o + HW_),     m);
        __stcs(reinterpret_cast<float4*>(o + 2 * HW_), make_float4(m.y, m.z, m.w, right));
    }
}

extern "C" void kernel_launch(void* const* d_in, const int* in_sizes, int n_in,
                              void* d_out, int out_size)
{
    const float* x = (const float*)d_in[0];
    float* out = (float*)d_out;
    unfold_kernel<<<NTHREADS_ / 256, 256>>>(x, out);
}